// round 12
// baseline (speedup 1.0000x reference)
#include <cuda_runtime.h>
#include <cuda_bf16.h>
#include <math.h>
#include <mma.h>
using namespace nvcuda;

// Problem dims
#define NB   256
#define NPG  64
#define DEG  8
#define NN   (NB*NPG)         // 16384
#define NE   (NN*DEG)         // 131072
#define NODE_IN 64
#define EDGE_IN 32
#define HD   256
#define NL   4
#define HEADS 8
#define DK   32
#define FF   512
#define QKV3 (3*HD)

// ---------------- scratch (device globals) ---------------------------------
__device__ float d_h[NN*HD];
__device__ float d_m[NN*HD];
__device__ float d_s3[NL*NE];
__device__ float d_w3c[NL*33];
__device__ float d_qkv[NN*QKV3];
__device__ float d_tmp[NN*HD];
__device__ float d_g[NN];
// bf16 hi/lo operand buffers (row-major)
__device__ __nv_bfloat16 d_nf_h[NN*NODE_IN],  d_nf_l[NN*NODE_IN];
__device__ __nv_bfloat16 d_wn_h[NODE_IN*HD],  d_wn_l[NODE_IN*HD];
__device__ __nv_bfloat16 d_gw_h[NL*HD*HD],    d_gw_l[NL*HD*HD];
__device__ __nv_bfloat16 d_wqkv_h[HD*QKV3],   d_wqkv_l[HD*QKV3];
__device__ __nv_bfloat16 d_ff1_h[HD*FF],      d_ff1_l[HD*FF];
__device__ __nv_bfloat16 d_ff2_h[FF*HD],      d_ff2_l[FF*HD];
__device__ __nv_bfloat16 d_g1_h[HD*HD],       d_g1_l[HD*HD];
__device__ __nv_bfloat16 d_hx_h[NN*HD],       d_hx_l[NN*HD];
__device__ __nv_bfloat16 d_ffx_h[NN*FF],      d_ffx_l[NN*FF];

// ---------------- helpers ---------------------------------------------------
__device__ __forceinline__ void bf16split(float x, __nv_bfloat16& h, __nv_bfloat16& l) {
    h = __float2bfloat16_rn(x);
    l = __float2bfloat16_rn(x - __bfloat162float(h));
}
__device__ __forceinline__ void cp16(void* smem_dst, const void* gmem_src) {
    unsigned s = (unsigned)__cvta_generic_to_shared(smem_dst);
    asm volatile("cp.async.cg.shared.global [%0], [%1], 16;\n" :: "r"(s), "l"(gmem_src));
}
#define CP_COMMIT() asm volatile("cp.async.commit_group;\n" ::: "memory")
#define CP_WAIT(n)  asm volatile("cp.async.wait_group %0;\n" :: "n"(n) : "memory")

// ---------------- generic fp32 -> bf16 hi/lo split --------------------------
__global__ void split_kernel(const float* __restrict__ src,
                             __nv_bfloat16* __restrict__ hi,
                             __nv_bfloat16* __restrict__ lo, int n) {
    int i = blockIdx.x * 256 + threadIdx.x;
    if (i < n) {
        __nv_bfloat16 h, l;
        bf16split(src[i], h, l);
        hi[i] = h; lo[i] = l;
    }
}

// ---------------- pack + split Wq|Wk|Wv into [HD][768] hi/lo ----------------
__global__ void pack_qkv_kernel(const float* __restrict__ Wq, const float* __restrict__ Wk,
                                const float* __restrict__ Wv,
                                __nv_bfloat16* __restrict__ Wh, __nv_bfloat16* __restrict__ Wl) {
    int idx = blockIdx.x * blockDim.x + threadIdx.x;
    if (idx < HD * HD) {
        int r = idx / HD, c = idx % HD;
        __nv_bfloat16 h, l;
        bf16split(Wq[idx], h, l); Wh[r*QKV3 + c] = h;        Wl[r*QKV3 + c] = l;
        bf16split(Wk[idx], h, l); Wh[r*QKV3 + HD + c] = h;   Wl[r*QKV3 + HD + c] = l;
        bf16split(Wv[idx], h, l); Wh[r*QKV3 + 2*HD + c] = h; Wl[r*QKV3 + 2*HD + c] = l;
    }
}

// ============ 3xBF16 GEMM, 64x64 warp tiles, pre-split operands =============
// C = act(A@B + bias); A,B given as bf16 hi/lo. M%128==0, N%256==0, K%32==0.
#define BM 128
#define BN 256
#define BK 32
#define A_LD 40                   // bf16 elems (32 + 8 pad)
#define B_LD 264                  // bf16 elems (256 + 8 pad)
#define A_STAGE (BM*A_LD)         // 5120
#define B_STAGE (BK*B_LD)         // 8448
#define GEMM_SMEM_BYTES ((2*2*A_STAGE + 2*2*B_STAGE)*2)   // 108544

__global__ __launch_bounds__(256) void gemm_bf3(
        const __nv_bfloat16* __restrict__ Ah_g, const __nv_bfloat16* __restrict__ Al_g,
        const __nv_bfloat16* __restrict__ Bh_g, const __nv_bfloat16* __restrict__ Bl_g,
        const float* __restrict__ bias, float* __restrict__ C,
        __nv_bfloat16* __restrict__ Chi, __nv_bfloat16* __restrict__ Clo,
        int M, int N, int K, int act) {
    extern __shared__ __align__(16) char smem_raw[];
    __nv_bfloat16* Ah = (__nv_bfloat16*)smem_raw;   // [2][A_STAGE]
    __nv_bfloat16* Al = Ah + 2*A_STAGE;
    __nv_bfloat16* Bh = Al + 2*A_STAGE;             // [2][B_STAGE]
    __nv_bfloat16* Bl = Bh + 2*B_STAGE;

    int tid = threadIdx.x;
    int warpId = tid >> 5;
    int lane = tid & 31;
    int wr = warpId & 1;          // 2 warp-rows of 64
    int wc = warpId >> 1;         // 4 warp-cols of 64
    int rowBase = blockIdx.y * BM;
    int colBase = blockIdx.x * BN;

    wmma::fragment<wmma::accumulator, 16, 16, 16, float> acc[4][4];
    #pragma unroll
    for (int i = 0; i < 4; i++)
        #pragma unroll
        for (int j = 0; j < 4; j++)
            wmma::fill_fragment(acc[i][j], 0.0f);

    auto issue_tile = [&](int buf, int k0) {
        __nv_bfloat16* AhS = Ah + buf*A_STAGE;
        __nv_bfloat16* AlS = Al + buf*A_STAGE;
        __nv_bfloat16* BhS = Bh + buf*B_STAGE;
        __nv_bfloat16* BlS = Bl + buf*B_STAGE;
        // A: 128x32 = 512 chunks of 8 bf16 (16B)
        #pragma unroll
        for (int q = 0; q < 2; q++) {
            int c = tid + q*256;
            int arow = c >> 2, acol = (c & 3) * 8;
            cp16(&AhS[arow*A_LD + acol], &Ah_g[(size_t)(rowBase + arow)*K + k0 + acol]);
            cp16(&AlS[arow*A_LD + acol], &Al_g[(size_t)(rowBase + arow)*K + k0 + acol]);
        }
        // B: 32x256 = 1024 chunks of 8 bf16
        #pragma unroll
        for (int q = 0; q < 4; q++) {
            int c = tid + q*256;
            int brow = c >> 5, bcol = (c & 31) * 8;
            cp16(&BhS[brow*B_LD + bcol], &Bh_g[(size_t)(k0 + brow)*N + colBase + bcol]);
            cp16(&BlS[brow*B_LD + bcol], &Bl_g[(size_t)(k0 + brow)*N + colBase + bcol]);
        }
        CP_COMMIT();
    };

    issue_tile(0, 0);

    int KT = K / BK;
    for (int kt = 0; kt < KT; kt++) {
        int buf = kt & 1;
        if (kt + 1 < KT) {
            issue_tile(buf ^ 1, (kt + 1) * BK);
            CP_WAIT(1);
        } else {
            CP_WAIT(0);
        }
        __syncthreads();

        const __nv_bfloat16* AhB = Ah + buf*A_STAGE;
        const __nv_bfloat16* AlB = Al + buf*A_STAGE;
        const __nv_bfloat16* BhB = Bh + buf*B_STAGE;
        const __nv_bfloat16* BlB = Bl + buf*B_STAGE;

        #pragma unroll
        for (int ks = 0; ks < BK; ks += 16) {
            wmma::fragment<wmma::matrix_b, 16, 16, 16, __nv_bfloat16, wmma::row_major> fbh[4], fbl[4];
            #pragma unroll
            for (int j = 0; j < 4; j++) {
                wmma::load_matrix_sync(fbh[j], &BhB[ks*B_LD + wc*64 + j*16], B_LD);
                wmma::load_matrix_sync(fbl[j], &BlB[ks*B_LD + wc*64 + j*16], B_LD);
            }
            #pragma unroll
            for (int i = 0; i < 4; i++) {
                wmma::fragment<wmma::matrix_a, 16, 16, 16, __nv_bfloat16, wmma::row_major> fah, fal;
                wmma::load_matrix_sync(fah, &AhB[(wr*64 + i*16)*A_LD + ks], A_LD);
                wmma::load_matrix_sync(fal, &AlB[(wr*64 + i*16)*A_LD + ks], A_LD);
                #pragma unroll
                for (int j = 0; j < 4; j++) {
                    wmma::mma_sync(acc[i][j], fah, fbl[j], acc[i][j]);
                    wmma::mma_sync(acc[i][j], fal, fbh[j], acc[i][j]);
                    wmma::mma_sync(acc[i][j], fah, fbh[j], acc[i][j]);
                }
            }
        }
        __syncthreads();
    }

    // epilogue: per-warp smem staging (mainloop done; smem reusable)
    float* stage = (float*)smem_raw + warpId * 320;   // 16x20 per warp
    #pragma unroll
    for (int i = 0; i < 4; i++) {
        #pragma unroll
        for (int j = 0; j < 4; j++) {
            wmma::store_matrix_sync(stage, acc[i][j], 20, wmma::mem_row_major);
            __syncwarp();
            #pragma unroll
            for (int t = 0; t < 8; t++) {
                int idx = lane + 32*t;
                int r = idx >> 4, c = idx & 15;
                int grow = rowBase + wr*64 + i*16 + r;
                int gcol = colBase + wc*64 + j*16 + c;
                float v = stage[r*20 + c] + (bias ? bias[gcol] : 0.0f);
                if (act == 1) v = fmaxf(v, 0.0f);
                else if (act == 2) v = 0.5f * v * (1.0f + erff(v * 0.70710678118654752f));
                size_t o = (size_t)grow * N + gcol;
                if (C) C[o] = v;
                if (Chi) {
                    __nv_bfloat16 hh, ll;
                    bf16split(v, hh, ll);
                    Chi[o] = hh; Clo[o] = ll;
                }
            }
            __syncwarp();
        }
    }
}

// ---------------- w3/c3 + s3 precompute ------------------------------------
__global__ void edge_w3_all_kernel(const float* __restrict__ We, const float* __restrict__ be,
                                   const float* __restrict__ gat_a, float* __restrict__ w3c) {
    int i = threadIdx.x;
    int l = i / 33, r = i % 33;
    if (i < NL * 33) {
        const float* a3 = gat_a + l * 3 * HD + 2 * HD;
        const float* row = (r < 32) ? (We + r * HD) : be;
        float acc = 0.0f;
        for (int hh = 0; hh < HD; hh++) acc = fmaf(row[hh], a3[hh], acc);
        w3c[l * 33 + r] = acc;
    }
}

__global__ void edge_s3_all_kernel(const float* __restrict__ ef, const float* __restrict__ w3c,
                                   float* __restrict__ s3all) {
    int e = blockIdx.x * 8 + (threadIdx.x >> 5);
    int lane = threadIdx.x & 31;
    float f = ef[e * EDGE_IN + lane];
    #pragma unroll
    for (int l = 0; l < NL; l++) {
        float v = f * w3c[l * 33 + lane];
        #pragma unroll
        for (int o = 16; o; o >>= 1) v += __shfl_xor_sync(0xffffffffu, v, o);
        if (lane == 0) s3all[l * NE + e] = v + w3c[l * 33 + 32];
    }
}

// ============ fused GAT layer tail: block = one graph (64 nodes) ============
#define M_LD 260
#define GAT_SMEM_BYTES ((64*M_LD + 64 + 64 + 512 + 512 + 512)*4)

__device__ __forceinline__ float warp_sum(float v) {
    #pragma unroll
    for (int o = 16; o; o >>= 1) v += __shfl_xor_sync(0xffffffffu, v, o);
    return v;
}

__global__ __launch_bounds__(256) void gat_fused_kernel(
        const float* __restrict__ m, const int* __restrict__ dst,
        const float* __restrict__ s3, const float* __restrict__ a12,
        const float* __restrict__ gamma, const float* __restrict__ beta,
        float* __restrict__ h,
        __nv_bfloat16* __restrict__ h_hi, __nv_bfloat16* __restrict__ h_lo) {
    extern __shared__ float sm[];
    float* m_s   = sm;
    float* s1_s  = m_s + 64*M_LD;
    float* s2_s  = s1_s + 64;
    float* w_s   = s2_s + 64;
    int*   dl_s  = (int*)(w_s + 512);
    float* a_s   = (float*)(dl_s + 512);

    int g = blockIdx.x;
    int tid = threadIdx.x;
    int warpId = tid >> 5;
    int lane = tid & 31;

    a_s[tid] = a12[tid];
    a_s[tid + 256] = a12[tid + 256];

    const float4* src = (const float4*)(m + (size_t)g * 64 * HD);
    #pragma unroll
    for (int q = 0; q < 16; q++) {
        int i = tid + q * 256;
        int n = i >> 6, c = i & 63;
        *(float4*)&m_s[n * M_LD + c * 4] = src[i];
    }
    __syncthreads();

    #pragma unroll
    for (int j = 0; j < 8; j++) {
        int n = warpId * 8 + j;
        float a1 = 0.0f, a2 = 0.0f;
        #pragma unroll
        for (int i = 0; i < 8; i++) {
            int dd = lane + 32 * i;
            float v = m_s[n * M_LD + dd];
            a1 = fmaf(v, a_s[dd], a1);
            a2 = fmaf(v, a_s[256 + dd], a2);
        }
        a1 = warp_sum(a1); a2 = warp_sum(a2);
        if (lane == 0) { s1_s[n] = a1; s2_s[n] = a2; }
    }
    __syncthreads();

    if (tid < 64) {
        int n = tid;
        size_t ebase = ((size_t)g * 64 + n) * DEG;
        float lg[DEG]; int dl[DEG];
        #pragma unroll
        for (int e = 0; e < DEG; e++) {
            int dn = dst[ebase + e];
            dl[e] = dn - g * 64;
            float L = s1_s[n] + s2_s[dl[e]] + s3[ebase + e];
            lg[e] = (L >= 0.0f) ? L : 0.01f * L;
        }
        float mx = -1e30f;
        #pragma unroll
        for (int e = 0; e < DEG; e++) mx = fmaxf(mx, lg[e]);
        float den = 0.0f;
        #pragma unroll
        for (int e = 0; e < DEG; e++) { lg[e] = expf(lg[e] - mx); den += lg[e]; }
        float inv = 1.0f / den;
        #pragma unroll
        for (int e = 0; e < DEG; e++) { w_s[n * DEG + e] = lg[e] * inv; dl_s[n * DEG + e] = dl[e]; }
    }
    __syncthreads();

    #pragma unroll
    for (int j = 0; j < 8; j++) {
        int n = warpId * 8 + j;
        float wgt[DEG]; int dl[DEG];
        #pragma unroll
        for (int e = 0; e < DEG; e++) { wgt[e] = w_s[n * DEG + e]; dl[e] = dl_s[n * DEG + e]; }
        size_t hbase = ((size_t)g * 64 + n) * HD;
        float vv[8];
        float ssum = 0.0f;
        #pragma unroll
        for (int i = 0; i < 8; i++) {
            int dd = lane + 32 * i;
            float agg = 0.0f;
            #pragma unroll
            for (int e = 0; e < DEG; e++)
                agg = fmaf(wgt[e], m_s[dl[e] * M_LD + dd], agg);
            vv[i] = agg + h[hbase + dd];
            ssum += vv[i];
        }
        float mu = warp_sum(ssum) * (1.0f / HD);
        float vsum = 0.0f;
        #pragma unroll
        for (int i = 0; i < 8; i++) { float dv = vv[i] - mu; vsum += dv * dv; }
        float inv = rsqrtf(warp_sum(vsum) * (1.0f / HD) + 1e-5f);
        #pragma unroll
        for (int i = 0; i < 8; i++) {
            int dd = lane + 32 * i;
            float o = (vv[i] - mu) * inv * gamma[dd] + beta[dd];
            h[hbase + dd] = o;
            __nv_bfloat16 hh, ll;
            bf16split(o, hh, ll);
            h_hi[hbase + dd] = hh; h_lo[hbase + dd] = ll;
        }
    }
}

// ---------------- MHA on packed qkv [NN][768] ------------------------------
__global__ void mha_kernel(const float* __restrict__ qkv, float* __restrict__ o) {
    int b = blockIdx.x / HEADS, hd = blockIdx.x % HEADS;
    int t = threadIdx.x;
    __shared__ float ks[NPG][DK];
    __shared__ float vs[NPG][DK];
    size_t rowb = (size_t)(b * NPG + t) * QKV3 + hd * DK;
    #pragma unroll
    for (int i = 0; i < DK; i++) {
        ks[t][i] = qkv[rowb + HD + i];
        vs[t][i] = qkv[rowb + 2*HD + i];
    }
    __syncthreads();
    float qr[DK];
    #pragma unroll
    for (int i = 0; i < DK; i++) qr[i] = qkv[rowb + i];
    float sc[NPG];
    float mx = -1e30f;
    const float scale = 0.17677669529663687f;
    for (int j = 0; j < NPG; j++) {
        float s = 0.0f;
        #pragma unroll
        for (int i = 0; i < DK; i++) s = fmaf(qr[i], ks[j][i], s);
        s *= scale;
        sc[j] = s;
        mx = fmaxf(mx, s);
    }
    float den = 0.0f;
    for (int j = 0; j < NPG; j++) { sc[j] = expf(sc[j] - mx); den += sc[j]; }
    float acc[DK];
    #pragma unroll
    for (int i = 0; i < DK; i++) acc[i] = 0.0f;
    for (int j = 0; j < NPG; j++) {
        float wj = sc[j];
        #pragma unroll
        for (int i = 0; i < DK; i++) acc[i] = fmaf(wj, vs[j][i], acc[i]);
    }
    float inv = 1.0f / den;
    size_t obase = (size_t)(b * NPG + t) * HD + hd * DK;
    #pragma unroll
    for (int i = 0; i < DK; i++) o[obase + i] = acc[i] * inv;
}

// ---------------- add + LN (+ bf16 hi/lo out) ------------------------------
__device__ __forceinline__ float block_reduce_sum(float v, float* sh) {
    int t = threadIdx.x;
    sh[t] = v;
    __syncthreads();
    #pragma unroll
    for (int s = 128; s > 0; s >>= 1) {
        if (t < s) sh[t] += sh[t + s];
        __syncthreads();
    }
    float r = sh[0];
    __syncthreads();
    return r;
}

__global__ void add_ln_kernel(const float* __restrict__ a, const float* __restrict__ b,
                              const float* __restrict__ gamma, const float* __restrict__ beta,
                              float eps, float* __restrict__ out,
                              __nv_bfloat16* __restrict__ ohi, __nv_bfloat16* __restrict__ olo) {
    int n = blockIdx.x, d = threadIdx.x;
    __shared__ float sh[256];
    float v = a[n * HD + d] + b[n * HD + d];
    float mu = block_reduce_sum(v, sh) * (1.0f / HD);
    float dv = v - mu;
    float var = block_reduce_sum(dv * dv, sh) * (1.0f / HD);
    float inv = rsqrtf(var + eps);
    float o = dv * inv * gamma[d] + beta[d];
    size_t idx = (size_t)n * HD + d;
    out[idx] = o;
    if (ohi) {
        __nv_bfloat16 hh, ll;
        bf16split(o, hh, ll);
        ohi[idx] = hh; olo[idx] = ll;
    }
}

// ---------------- gate scalar + readout ------------------------------------
__global__ void gate_g_kernel(const float* __restrict__ r, const float* __restrict__ w,
                              const float* __restrict__ b2, float* __restrict__ g) {
    int n = blockIdx.x * 8 + (threadIdx.x >> 5);
    int lane = threadIdx.x & 31;
    float acc = 0.0f;
    #pragma unroll
    for (int i = lane; i < HD; i += 32) acc = fmaf(r[n * HD + i], w[i], acc);
    #pragma unroll
    for (int o = 16; o; o >>= 1) acc += __shfl_xor_sync(0xffffffffu, acc, o);
    if (lane == 0) g[n] = acc + b2[0];
}

__global__ void readout_kernel(const float* __restrict__ x, const float* __restrict__ g,
                               float* __restrict__ out) {
    int b = blockIdx.x, d = threadIdx.x;
    __shared__ float sg[NPG];
    if (d < NPG) sg[d] = g[b * NPG + d];
    __syncthreads();
    float mx = -1e30f;
    #pragma unroll
    for (int i = 0; i < NPG; i++) mx = fmaxf(mx, sg[i]);
    float den = 0.0f;
    #pragma unroll
    for (int i = 0; i < NPG; i++) den += expf(sg[i] - mx);
    float inv = 1.0f / den;
    float acc = 0.0f;
    for (int i = 0; i < NPG; i++) {
        float wi = expf(sg[i] - mx) * inv;
        acc = fmaf(wi, x[(b * NPG + i) * HD + d], acc);
    }
    out[b * HD + d] = acc;
}

// ===========================================================================
extern "C" void kernel_launch(void* const* d_in, const int* in_sizes, int n_in,
                              void* d_out, int out_size) {
    const float* node_feats = (const float*)d_in[0];
    const float* edge_feats = (const float*)d_in[1];
    const int*   dst        = (const int*)d_in[3];
    const float* Wn = (const float*)d_in[4];
    const float* bn = (const float*)d_in[5];
    const float* We = (const float*)d_in[6];
    const float* be = (const float*)d_in[7];
    const float* gat_W   = (const float*)d_in[8];
    const float* gat_a   = (const float*)d_in[9];
    const float* gat_lng = (const float*)d_in[10];
    const float* gat_lnb = (const float*)d_in[11];
    const float* Wq = (const float*)d_in[12];
    const float* Wk = (const float*)d_in[13];
    const float* Wv = (const float*)d_in[14];
    const float* att_lng = (const float*)d_in[15];
    const float* att_lnb = (const float*)d_in[16];
    const float* ff_W1 = (const float*)d_in[17];
    const float* ff_b1 = (const float*)d_in[18];
    const float* ff_W2 = (const float*)d_in[19];
    const float* ff_b2 = (const float*)d_in[20];
    const float* ff_lng = (const float*)d_in[21];
    const float* ff_lnb = (const float*)d_in[22];
    const float* g_W1 = (const float*)d_in[23];
    const float* g_b1 = (const float*)d_in[24];
    const float* g_W2 = (const float*)d_in[25];
    const float* g_b2 = (const float*)d_in[26];
    float* out = (float*)d_out;

    float *h, *m, *s3, *w3c, *qkv, *tmp, *g;
    __nv_bfloat16 *nf_h, *nf_l, *wn_h, *wn_l, *gw_h, *gw_l, *wqkv_h, *wqkv_l;
    __nv_bfloat16 *ff1_h, *ff1_l, *ff2_h, *ff2_l, *g1_h, *g1_l;
    __nv_bfloat16 *hx_h, *hx_l, *ffx_h, *ffx_l;
    cudaGetSymbolAddress((void**)&h,    d_h);
    cudaGetSymbolAddress((void**)&m,    d_m);
    cudaGetSymbolAddress((void**)&s3,   d_s3);
    cudaGetSymbolAddress((void**)&w3c,  d_w3c);
    cudaGetSymbolAddress((void**)&qkv,  d_qkv);
    cudaGetSymbolAddress((void**)&tmp,  d_tmp);
    cudaGetSymbolAddress((void**)&g,    d_g);
    cudaGetSymbolAddress((void**)&nf_h, d_nf_h);  cudaGetSymbolAddress((void**)&nf_l, d_nf_l);
    cudaGetSymbolAddress((void**)&wn_h, d_wn_h);  cudaGetSymbolAddress((void**)&wn_l, d_wn_l);
    cudaGetSymbolAddress((void**)&gw_h, d_gw_h);  cudaGetSymbolAddress((void**)&gw_l, d_gw_l);
    cudaGetSymbolAddress((void**)&wqkv_h, d_wqkv_h); cudaGetSymbolAddress((void**)&wqkv_l, d_wqkv_l);
    cudaGetSymbolAddress((void**)&ff1_h, d_ff1_h); cudaGetSymbolAddress((void**)&ff1_l, d_ff1_l);
    cudaGetSymbolAddress((void**)&ff2_h, d_ff2_h); cudaGetSymbolAddress((void**)&ff2_l, d_ff2_l);
    cudaGetSymbolAddress((void**)&g1_h, d_g1_h);  cudaGetSymbolAddress((void**)&g1_l, d_g1_l);
    cudaGetSymbolAddress((void**)&hx_h, d_hx_h);  cudaGetSymbolAddress((void**)&hx_l, d_hx_l);
    cudaGetSymbolAddress((void**)&ffx_h, d_ffx_h); cudaGetSymbolAddress((void**)&ffx_l, d_ffx_l);

    static bool attr_done = false;
    if (!attr_done) {
        cudaFuncSetAttribute(gemm_bf3, cudaFuncAttributeMaxDynamicSharedMemorySize, GEMM_SMEM_BYTES);
        cudaFuncSetAttribute(gat_fused_kernel, cudaFuncAttributeMaxDynamicSharedMemorySize, GAT_SMEM_BYTES);
        attr_done = true;
    }

    // --- operand pre-splits (weights + input) ---
    split_kernel<<<(NN*NODE_IN + 255)/256, 256>>>(node_feats, nf_h, nf_l, NN*NODE_IN);
    split_kernel<<<(NODE_IN*HD + 255)/256, 256>>>(Wn, wn_h, wn_l, NODE_IN*HD);
    split_kernel<<<(NL*HD*HD + 255)/256, 256>>>(gat_W, gw_h, gw_l, NL*HD*HD);
    split_kernel<<<(HD*FF + 255)/256, 256>>>(ff_W1, ff1_h, ff1_l, HD*FF);
    split_kernel<<<(FF*HD + 255)/256, 256>>>(ff_W2, ff2_h, ff2_l, FF*HD);
    split_kernel<<<(HD*HD + 255)/256, 256>>>(g_W1, g1_h, g1_l, HD*HD);
    pack_qkv_kernel<<<(HD*HD + 255)/256, 256>>>(Wq, Wk, Wv, wqkv_h, wqkv_l);
    edge_w3_all_kernel<<<1, NL*33>>>(We, be, gat_a, w3c);
    edge_s3_all_kernel<<<NE/8, 256>>>(edge_feats, w3c, s3);

    // h = node_feats @ Wn + bn  (also emit hi/lo)
    gemm_bf3<<<dim3(HD/BN, NN/BM), 256, GEMM_SMEM_BYTES>>>(
        nf_h, nf_l, wn_h, wn_l, bn, h, hx_h, hx_l, NN, HD, NODE_IN, 0);

    // GAT layers
    for (int l = 0; l < NL; l++) {
        gemm_bf3<<<dim3(HD/BN, NN/BM), 256, GEMM_SMEM_BYTES>>>(
            hx_h, hx_l, gw_h + (size_t)l*HD*HD, gw_l + (size_t)l*HD*HD,
            nullptr, m, nullptr, nullptr, NN, HD, HD, 0);
        gat_fused_kernel<<<NB, 256, GAT_SMEM_BYTES>>>(
            m, dst, s3 + (size_t)l*NE, gat_a + (size_t)l*3*HD,
            gat_lng + l*HD, gat_lnb + l*HD, h, hx_h, hx_l);
    }

    // QKV + attention + LN
    gemm_bf3<<<dim3(QKV3/BN, NN/BM), 256, GEMM_SMEM_BYTES>>>(
        hx_h, hx_l, wqkv_h, wqkv_l, nullptr, qkv, nullptr, nullptr, NN, QKV3, HD, 0);
    mha_kernel<<<NB * HEADS, NPG>>>(qkv, tmp);
    add_ln_kernel<<<NN, 256>>>(tmp, h, att_lng, att_lnb, 1e-6f, h, hx_h, hx_l);

    // FFN
    gemm_bf3<<<dim3(FF/BN, NN/BM), 256, GEMM_SMEM_BYTES>>>(
        hx_h, hx_l, ff1_h, ff1_l, ff_b1, nullptr, ffx_h, ffx_l, NN, FF, HD, 2);
    gemm_bf3<<<dim3(HD/BN, NN/BM), 256, GEMM_SMEM_BYTES>>>(
        ffx_h, ffx_l, ff2_h, ff2_l, ff_b2, tmp, nullptr, nullptr, NN, HD, FF, 0);
    add_ln_kernel<<<NN, 256>>>(h, tmp, ff_lng, ff_lnb, 1e-6f, h, hx_h, hx_l);

    // Gating readout
    gemm_bf3<<<dim3(HD/BN, NN/BM), 256, GEMM_SMEM_BYTES>>>(
        hx_h, hx_l, g1_h, g1_l, g_b1, m, nullptr, nullptr, NN, HD, HD, 1);
    gate_g_kernel<<<NN/8, 256>>>(m, g_W2, g_b2, g);
    readout_kernel<<<NB, HD>>>(h, g, out);

    (void)in_sizes; (void)n_in; (void)out_size;
}

// round 13
// speedup vs baseline: 1.0933x; 1.0933x over previous
#include <cuda_runtime.h>
#include <cuda_bf16.h>
#include <math.h>
#include <mma.h>
using namespace nvcuda;

// Problem dims
#define NB   256
#define NPG  64
#define DEG  8
#define NN   (NB*NPG)         // 16384
#define NE   (NN*DEG)         // 131072
#define NODE_IN 64
#define EDGE_IN 32
#define HD   256
#define NL   4
#define HEADS 8
#define DK   32
#define FF   512
#define QKV3 (3*HD)

// ---------------- scratch (device globals) ---------------------------------
__device__ float d_h[NN*HD];
__device__ float d_m[NN*HD];
__device__ float d_s3[NL*NE];
__device__ float d_w3c[NL*33];
__device__ float d_qkv[NN*QKV3];
__device__ float d_tmp[NN*HD];
__device__ float d_g[NN];
// bf16 hi/lo operand buffers (row-major)
__device__ __nv_bfloat16 d_nf_h[NN*NODE_IN],  d_nf_l[NN*NODE_IN];
__device__ __nv_bfloat16 d_wn_h[NODE_IN*HD],  d_wn_l[NODE_IN*HD];
__device__ __nv_bfloat16 d_gw_h[NL*HD*HD],    d_gw_l[NL*HD*HD];
__device__ __nv_bfloat16 d_wqkv_h[HD*QKV3],   d_wqkv_l[HD*QKV3];
__device__ __nv_bfloat16 d_ff1_h[HD*FF],      d_ff1_l[HD*FF];
__device__ __nv_bfloat16 d_ff2_h[FF*HD],      d_ff2_l[FF*HD];
__device__ __nv_bfloat16 d_g1_h[HD*HD],       d_g1_l[HD*HD];
__device__ __nv_bfloat16 d_hx_h[NN*HD],       d_hx_l[NN*HD];
__device__ __nv_bfloat16 d_ffx_h[NN*FF],      d_ffx_l[NN*FF];

// ---------------- helpers ---------------------------------------------------
__device__ __forceinline__ void bf16split(float x, __nv_bfloat16& h, __nv_bfloat16& l) {
    h = __float2bfloat16_rn(x);
    l = __float2bfloat16_rn(x - __bfloat162float(h));
}
__device__ __forceinline__ void cp16(void* smem_dst, const void* gmem_src) {
    unsigned s = (unsigned)__cvta_generic_to_shared(smem_dst);
    asm volatile("cp.async.cg.shared.global [%0], [%1], 16;\n" :: "r"(s), "l"(gmem_src));
}
#define CP_COMMIT() asm volatile("cp.async.commit_group;\n" ::: "memory")
#define CP_WAIT(n)  asm volatile("cp.async.wait_group %0;\n" :: "n"(n) : "memory")

// ============ merged weight prep: all weight splits + QKV pack ==============
// segments (element offsets in a virtual concatenation):
//   [0,16384)          Wn        -> wn_h/l
//   [16384,278528)     gat_W     -> gw_h/l
//   [278528,409600)    ff_W1     -> ff1_h/l
//   [409600,540672)    ff_W2     -> ff2_h/l
//   [540672,606208)    g_W1      -> g1_h/l
//   [606208,671744)    qkv pack  (reads Wq/Wk/Wv[idx], writes 3 slots each)
#define PREPW_TOTAL 671744

__global__ void prep_weights_kernel(
        const float* __restrict__ Wn, const float* __restrict__ gat_W,
        const float* __restrict__ ff_W1, const float* __restrict__ ff_W2,
        const float* __restrict__ g_W1,
        const float* __restrict__ Wq, const float* __restrict__ Wk, const float* __restrict__ Wv,
        __nv_bfloat16* __restrict__ wn_h, __nv_bfloat16* __restrict__ wn_l,
        __nv_bfloat16* __restrict__ gw_h, __nv_bfloat16* __restrict__ gw_l,
        __nv_bfloat16* __restrict__ ff1_h, __nv_bfloat16* __restrict__ ff1_l,
        __nv_bfloat16* __restrict__ ff2_h, __nv_bfloat16* __restrict__ ff2_l,
        __nv_bfloat16* __restrict__ g1_h, __nv_bfloat16* __restrict__ g1_l,
        __nv_bfloat16* __restrict__ wqkv_h, __nv_bfloat16* __restrict__ wqkv_l) {
    int i = blockIdx.x * 256 + threadIdx.x;
    if (i >= PREPW_TOTAL) return;
    __nv_bfloat16 h, l;
    if (i < 16384) {
        bf16split(Wn[i], h, l); wn_h[i] = h; wn_l[i] = l;
    } else if (i < 278528) {
        int j = i - 16384;
        bf16split(gat_W[j], h, l); gw_h[j] = h; gw_l[j] = l;
    } else if (i < 409600) {
        int j = i - 278528;
        bf16split(ff_W1[j], h, l); ff1_h[j] = h; ff1_l[j] = l;
    } else if (i < 540672) {
        int j = i - 409600;
        bf16split(ff_W2[j], h, l); ff2_h[j] = h; ff2_l[j] = l;
    } else if (i < 606208) {
        int j = i - 540672;
        bf16split(g_W1[j], h, l); g1_h[j] = h; g1_l[j] = l;
    } else {
        int j = i - 606208;           // 0..65535 over HD*HD
        int r = j / HD, c = j % HD;
        bf16split(Wq[j], h, l); wqkv_h[r*QKV3 + c] = h;        wqkv_l[r*QKV3 + c] = l;
        bf16split(Wk[j], h, l); wqkv_h[r*QKV3 + HD + c] = h;   wqkv_l[r*QKV3 + HD + c] = l;
        bf16split(Wv[j], h, l); wqkv_h[r*QKV3 + 2*HD + c] = h; wqkv_l[r*QKV3 + 2*HD + c] = l;
    }
}

// ---------------- node_feats split ------------------------------------------
__global__ void prep_nf_kernel(const float* __restrict__ src,
                               __nv_bfloat16* __restrict__ hi,
                               __nv_bfloat16* __restrict__ lo) {
    int i = blockIdx.x * 256 + threadIdx.x;
    if (i < NN * NODE_IN) {
        __nv_bfloat16 h, l;
        bf16split(src[i], h, l);
        hi[i] = h; lo[i] = l;
    }
}

// ============ 3xBF16 GEMM, 64x32 warp tiles, pre-split operands =============
// C = act(A@B + bias); A,B given as bf16 hi/lo. M%128==0, N%128==0, K%32==0.
#define BM 128
#define BN 128
#define BK 32
#define A_LD 40                   // bf16 elems (32 + 8 pad)
#define B_LD 136                  // bf16 elems (128 + 8 pad)
#define A_STAGE (BM*A_LD)         // 5120
#define B_STAGE (BK*B_LD)         // 4352
#define GEMM_SMEM_BYTES ((2*2*A_STAGE + 2*2*B_STAGE)*2)   // 75776

__global__ __launch_bounds__(256) void gemm_bf3(
        const __nv_bfloat16* __restrict__ Ah_g, const __nv_bfloat16* __restrict__ Al_g,
        const __nv_bfloat16* __restrict__ Bh_g, const __nv_bfloat16* __restrict__ Bl_g,
        const float* __restrict__ bias, float* __restrict__ C,
        __nv_bfloat16* __restrict__ Chi, __nv_bfloat16* __restrict__ Clo,
        int M, int N, int K, int act) {
    extern __shared__ __align__(16) char smem_raw[];
    __nv_bfloat16* Ah = (__nv_bfloat16*)smem_raw;   // [2][A_STAGE]
    __nv_bfloat16* Al = Ah + 2*A_STAGE;
    __nv_bfloat16* Bh = Al + 2*A_STAGE;             // [2][B_STAGE]
    __nv_bfloat16* Bl = Bh + 2*B_STAGE;

    int tid = threadIdx.x;
    int warpId = tid >> 5;
    int lane = tid & 31;
    int wr = warpId & 1;
    int wc = warpId >> 1;
    int rowBase = blockIdx.y * BM;
    int colBase = blockIdx.x * BN;

    wmma::fragment<wmma::accumulator, 16, 16, 16, float> acc[4][2];
    #pragma unroll
    for (int i = 0; i < 4; i++)
        #pragma unroll
        for (int j = 0; j < 2; j++)
            wmma::fill_fragment(acc[i][j], 0.0f);

    auto issue_tile = [&](int buf, int k0) {
        __nv_bfloat16* AhS = Ah + buf*A_STAGE;
        __nv_bfloat16* AlS = Al + buf*A_STAGE;
        __nv_bfloat16* BhS = Bh + buf*B_STAGE;
        __nv_bfloat16* BlS = Bl + buf*B_STAGE;
        #pragma unroll
        for (int q = 0; q < 2; q++) {
            int c = tid + q*256;
            int arow = c >> 2, acol = (c & 3) * 8;
            cp16(&AhS[arow*A_LD + acol], &Ah_g[(size_t)(rowBase + arow)*K + k0 + acol]);
            cp16(&AlS[arow*A_LD + acol], &Al_g[(size_t)(rowBase + arow)*K + k0 + acol]);
            int brow = c >> 4, bcol = (c & 15) * 8;
            cp16(&BhS[brow*B_LD + bcol], &Bh_g[(size_t)(k0 + brow)*N + colBase + bcol]);
            cp16(&BlS[brow*B_LD + bcol], &Bl_g[(size_t)(k0 + brow)*N + colBase + bcol]);
        }
        CP_COMMIT();
    };

    issue_tile(0, 0);

    int KT = K / BK;
    for (int kt = 0; kt < KT; kt++) {
        int buf = kt & 1;
        if (kt + 1 < KT) {
            issue_tile(buf ^ 1, (kt + 1) * BK);
            CP_WAIT(1);
        } else {
            CP_WAIT(0);
        }
        __syncthreads();

        const __nv_bfloat16* AhB = Ah + buf*A_STAGE;
        const __nv_bfloat16* AlB = Al + buf*A_STAGE;
        const __nv_bfloat16* BhB = Bh + buf*B_STAGE;
        const __nv_bfloat16* BlB = Bl + buf*B_STAGE;

        #pragma unroll
        for (int ks = 0; ks < BK; ks += 16) {
            wmma::fragment<wmma::matrix_b, 16, 16, 16, __nv_bfloat16, wmma::row_major> fbh[2], fbl[2];
            #pragma unroll
            for (int j = 0; j < 2; j++) {
                wmma::load_matrix_sync(fbh[j], &BhB[ks*B_LD + wc*32 + j*16], B_LD);
                wmma::load_matrix_sync(fbl[j], &BlB[ks*B_LD + wc*32 + j*16], B_LD);
            }
            #pragma unroll
            for (int i = 0; i < 4; i++) {
                wmma::fragment<wmma::matrix_a, 16, 16, 16, __nv_bfloat16, wmma::row_major> fah, fal;
                wmma::load_matrix_sync(fah, &AhB[(wr*64 + i*16)*A_LD + ks], A_LD);
                wmma::load_matrix_sync(fal, &AlB[(wr*64 + i*16)*A_LD + ks], A_LD);
                #pragma unroll
                for (int j = 0; j < 2; j++) {
                    wmma::mma_sync(acc[i][j], fah, fbl[j], acc[i][j]);
                    wmma::mma_sync(acc[i][j], fal, fbh[j], acc[i][j]);
                    wmma::mma_sync(acc[i][j], fah, fbh[j], acc[i][j]);
                }
            }
        }
        __syncthreads();
    }

    // epilogue
    float* stage = (float*)smem_raw + warpId * 320;   // 16x20 per warp
    #pragma unroll
    for (int i = 0; i < 4; i++) {
        #pragma unroll
        for (int j = 0; j < 2; j++) {
            wmma::store_matrix_sync(stage, acc[i][j], 20, wmma::mem_row_major);
            __syncwarp();
            #pragma unroll
            for (int t = 0; t < 8; t++) {
                int idx = lane + 32*t;
                int r = idx >> 4, c = idx & 15;
                int grow = rowBase + wr*64 + i*16 + r;
                int gcol = colBase + wc*32 + j*16 + c;
                float v = stage[r*20 + c] + (bias ? bias[gcol] : 0.0f);
                if (act == 1) v = fmaxf(v, 0.0f);
                else if (act == 2) v = 0.5f * v * (1.0f + erff(v * 0.70710678118654752f));
                size_t o = (size_t)grow * N + gcol;
                if (C) C[o] = v;
                if (Chi) {
                    __nv_bfloat16 hh, ll;
                    bf16split(v, hh, ll);
                    Chi[o] = hh; Clo[o] = ll;
                }
            }
            __syncwarp();
        }
    }
}

// ---------------- w3/c3 + s3 precompute ------------------------------------
__global__ void edge_w3_all_kernel(const float* __restrict__ We, const float* __restrict__ be,
                                   const float* __restrict__ gat_a, float* __restrict__ w3c) {
    int i = threadIdx.x;
    int l = i / 33, r = i % 33;
    if (i < NL * 33) {
        const float* a3 = gat_a + l * 3 * HD + 2 * HD;
        const float* row = (r < 32) ? (We + r * HD) : be;
        float acc = 0.0f;
        for (int hh = 0; hh < HD; hh++) acc = fmaf(row[hh], a3[hh], acc);
        w3c[l * 33 + r] = acc;
    }
}

__global__ void edge_s3_all_kernel(const float* __restrict__ ef, const float* __restrict__ w3c,
                                   float* __restrict__ s3all) {
    int e = blockIdx.x * 8 + (threadIdx.x >> 5);
    int lane = threadIdx.x & 31;
    float f = ef[e * EDGE_IN + lane];
    #pragma unroll
    for (int l = 0; l < NL; l++) {
        float v = f * w3c[l * 33 + lane];
        #pragma unroll
        for (int o = 16; o; o >>= 1) v += __shfl_xor_sync(0xffffffffu, v, o);
        if (lane == 0) s3all[l * NE + e] = v + w3c[l * 33 + 32];
    }
}

// ============ fused GAT layer tail: block = one graph (64 nodes) ============
#define M_LD 260
#define GAT_SMEM_BYTES ((64*M_LD + 64 + 64 + 512 + 512 + 512)*4)

__device__ __forceinline__ float warp_sum(float v) {
    #pragma unroll
    for (int o = 16; o; o >>= 1) v += __shfl_xor_sync(0xffffffffu, v, o);
    return v;
}

__global__ __launch_bounds__(256) void gat_fused_kernel(
        const float* __restrict__ m, const int* __restrict__ dst,
        const float* __restrict__ s3, const float* __restrict__ a12,
        const float* __restrict__ gamma, const float* __restrict__ beta,
        float* __restrict__ h,
        __nv_bfloat16* __restrict__ h_hi, __nv_bfloat16* __restrict__ h_lo) {
    extern __shared__ float sm[];
    float* m_s   = sm;
    float* s1_s  = m_s + 64*M_LD;
    float* s2_s  = s1_s + 64;
    float* w_s   = s2_s + 64;
    int*   dl_s  = (int*)(w_s + 512);
    float* a_s   = (float*)(dl_s + 512);

    int g = blockIdx.x;
    int tid = threadIdx.x;
    int warpId = tid >> 5;
    int lane = tid & 31;

    a_s[tid] = a12[tid];
    a_s[tid + 256] = a12[tid + 256];

    const float4* src = (const float4*)(m + (size_t)g * 64 * HD);
    #pragma unroll
    for (int q = 0; q < 16; q++) {
        int i = tid + q * 256;
        int n = i >> 6, c = i & 63;
        *(float4*)&m_s[n * M_LD + c * 4] = src[i];
    }
    __syncthreads();

    #pragma unroll
    for (int j = 0; j < 8; j++) {
        int n = warpId * 8 + j;
        float a1 = 0.0f, a2 = 0.0f;
        #pragma unroll
        for (int i = 0; i < 8; i++) {
            int dd = lane + 32 * i;
            float v = m_s[n * M_LD + dd];
            a1 = fmaf(v, a_s[dd], a1);
            a2 = fmaf(v, a_s[256 + dd], a2);
        }
        a1 = warp_sum(a1); a2 = warp_sum(a2);
        if (lane == 0) { s1_s[n] = a1; s2_s[n] = a2; }
    }
    __syncthreads();

    if (tid < 64) {
        int n = tid;
        size_t ebase = ((size_t)g * 64 + n) * DEG;
        float lg[DEG]; int dl[DEG];
        #pragma unroll
        for (int e = 0; e < DEG; e++) {
            int dn = dst[ebase + e];
            dl[e] = dn - g * 64;
            float L = s1_s[n] + s2_s[dl[e]] + s3[ebase + e];
            lg[e] = (L >= 0.0f) ? L : 0.01f * L;
        }
        float mx = -1e30f;
        #pragma unroll
        for (int e = 0; e < DEG; e++) mx = fmaxf(mx, lg[e]);
        float den = 0.0f;
        #pragma unroll
        for (int e = 0; e < DEG; e++) { lg[e] = expf(lg[e] - mx); den += lg[e]; }
        float inv = 1.0f / den;
        #pragma unroll
        for (int e = 0; e < DEG; e++) { w_s[n * DEG + e] = lg[e] * inv; dl_s[n * DEG + e] = dl[e]; }
    }
    __syncthreads();

    #pragma unroll
    for (int j = 0; j < 8; j++) {
        int n = warpId * 8 + j;
        float wgt[DEG]; int dl[DEG];
        #pragma unroll
        for (int e = 0; e < DEG; e++) { wgt[e] = w_s[n * DEG + e]; dl[e] = dl_s[n * DEG + e]; }
        size_t hbase = ((size_t)g * 64 + n) * HD;
        float vv[8];
        float ssum = 0.0f;
        #pragma unroll
        for (int i = 0; i < 8; i++) {
            int dd = lane + 32 * i;
            float agg = 0.0f;
            #pragma unroll
            for (int e = 0; e < DEG; e++)
                agg = fmaf(wgt[e], m_s[dl[e] * M_LD + dd], agg);
            vv[i] = agg + h[hbase + dd];
            ssum += vv[i];
        }
        float mu = warp_sum(ssum) * (1.0f / HD);
        float vsum = 0.0f;
        #pragma unroll
        for (int i = 0; i < 8; i++) { float dv = vv[i] - mu; vsum += dv * dv; }
        float inv = rsqrtf(warp_sum(vsum) * (1.0f / HD) + 1e-5f);
        #pragma unroll
        for (int i = 0; i < 8; i++) {
            int dd = lane + 32 * i;
            float o = (vv[i] - mu) * inv * gamma[dd] + beta[dd];
            h[hbase + dd] = o;
            __nv_bfloat16 hh, ll;
            bf16split(o, hh, ll);
            h_hi[hbase + dd] = hh; h_lo[hbase + dd] = ll;
        }
    }
}

// ---------------- MHA on packed qkv [NN][768] ------------------------------
__global__ void mha_kernel(const float* __restrict__ qkv, float* __restrict__ o) {
    int b = blockIdx.x / HEADS, hd = blockIdx.x % HEADS;
    int t = threadIdx.x;
    __shared__ float ks[NPG][DK];
    __shared__ float vs[NPG][DK];
    size_t rowb = (size_t)(b * NPG + t) * QKV3 + hd * DK;
    #pragma unroll
    for (int i = 0; i < DK; i++) {
        ks[t][i] = qkv[rowb + HD + i];
        vs[t][i] = qkv[rowb + 2*HD + i];
    }
    __syncthreads();
    float qr[DK];
    #pragma unroll
    for (int i = 0; i < DK; i++) qr[i] = qkv[rowb + i];
    float sc[NPG];
    float mx = -1e30f;
    const float scale = 0.17677669529663687f;
    for (int j = 0; j < NPG; j++) {
        float s = 0.0f;
        #pragma unroll
        for (int i = 0; i < DK; i++) s = fmaf(qr[i], ks[j][i], s);
        s *= scale;
        sc[j] = s;
        mx = fmaxf(mx, s);
    }
    float den = 0.0f;
    for (int j = 0; j < NPG; j++) { sc[j] = expf(sc[j] - mx); den += sc[j]; }
    float acc[DK];
    #pragma unroll
    for (int i = 0; i < DK; i++) acc[i] = 0.0f;
    for (int j = 0; j < NPG; j++) {
        float wj = sc[j];
        #pragma unroll
        for (int i = 0; i < DK; i++) acc[i] = fmaf(wj, vs[j][i], acc[i]);
    }
    float inv = 1.0f / den;
    size_t obase = (size_t)(b * NPG + t) * HD + hd * DK;
    #pragma unroll
    for (int i = 0; i < DK; i++) o[obase + i] = acc[i] * inv;
}

// ---------------- add + LN (+ bf16 hi/lo out) ------------------------------
__device__ __forceinline__ float block_reduce_sum(float v, float* sh) {
    int t = threadIdx.x;
    sh[t] = v;
    __syncthreads();
    #pragma unroll
    for (int s = 128; s > 0; s >>= 1) {
        if (t < s) sh[t] += sh[t + s];
        __syncthreads();
    }
    float r = sh[0];
    __syncthreads();
    return r;
}

__global__ void add_ln_kernel(const float* __restrict__ a, const float* __restrict__ b,
                              const float* __restrict__ gamma, const float* __restrict__ beta,
                              float eps, float* __restrict__ out,
                              __nv_bfloat16* __restrict__ ohi, __nv_bfloat16* __restrict__ olo) {
    int n = blockIdx.x, d = threadIdx.x;
    __shared__ float sh[256];
    float v = a[n * HD + d] + b[n * HD + d];
    float mu = block_reduce_sum(v, sh) * (1.0f / HD);
    float dv = v - mu;
    float var = block_reduce_sum(dv * dv, sh) * (1.0f / HD);
    float inv = rsqrtf(var + eps);
    float o = dv * inv * gamma[d] + beta[d];
    size_t idx = (size_t)n * HD + d;
    out[idx] = o;
    if (ohi) {
        __nv_bfloat16 hh, ll;
        bf16split(o, hh, ll);
        ohi[idx] = hh; olo[idx] = ll;
    }
}

// ---------------- gate scalar + readout ------------------------------------
__global__ void gate_g_kernel(const float* __restrict__ r, const float* __restrict__ w,
                              const float* __restrict__ b2, float* __restrict__ g) {
    int n = blockIdx.x * 8 + (threadIdx.x >> 5);
    int lane = threadIdx.x & 31;
    float acc = 0.0f;
    #pragma unroll
    for (int i = lane; i < HD; i += 32) acc = fmaf(r[n * HD + i], w[i], acc);
    #pragma unroll
    for (int o = 16; o; o >>= 1) acc += __shfl_xor_sync(0xffffffffu, acc, o);
    if (lane == 0) g[n] = acc + b2[0];
}

__global__ void readout_kernel(const float* __restrict__ x, const float* __restrict__ g,
                               float* __restrict__ out) {
    int b = blockIdx.x, d = threadIdx.x;
    __shared__ float sg[NPG];
    if (d < NPG) sg[d] = g[b * NPG + d];
    __syncthreads();
    float mx = -1e30f;
    #pragma unroll
    for (int i = 0; i < NPG; i++) mx = fmaxf(mx, sg[i]);
    float den = 0.0f;
    #pragma unroll
    for (int i = 0; i < NPG; i++) den += expf(sg[i] - mx);
    float inv = 1.0f / den;
    float acc = 0.0f;
    for (int i = 0; i < NPG; i++) {
        float wi = expf(sg[i] - mx) * inv;
        acc = fmaf(wi, x[(b * NPG + i) * HD + d], acc);
    }
    out[b * HD + d] = acc;
}

// ===========================================================================
extern "C" void kernel_launch(void* const* d_in, const int* in_sizes, int n_in,
                              void* d_out, int out_size) {
    const float* node_feats = (const float*)d_in[0];
    const float* edge_feats = (const float*)d_in[1];
    const int*   dst        = (const int*)d_in[3];
    const float* Wn = (const float*)d_in[4];
    const float* bn = (const float*)d_in[5];
    const float* We = (const float*)d_in[6];
    const float* be = (const float*)d_in[7];
    const float* gat_W   = (const float*)d_in[8];
    const float* gat_a   = (const float*)d_in[9];
    const float* gat_lng = (const float*)d_in[10];
    const float* gat_lnb = (const float*)d_in[11];
    const float* Wq = (const float*)d_in[12];
    const float* Wk = (const float*)d_in[13];
    const float* Wv = (const float*)d_in[14];
    const float* att_lng = (const float*)d_in[15];
    const float* att_lnb = (const float*)d_in[16];
    const float* ff_W1 = (const float*)d_in[17];
    const float* ff_b1 = (const float*)d_in[18];
    const float* ff_W2 = (const float*)d_in[19];
    const float* ff_b2 = (const float*)d_in[20];
    const float* ff_lng = (const float*)d_in[21];
    const float* ff_lnb = (const float*)d_in[22];
    const float* g_W1 = (const float*)d_in[23];
    const float* g_b1 = (const float*)d_in[24];
    const float* g_W2 = (const float*)d_in[25];
    const float* g_b2 = (const float*)d_in[26];
    float* out = (float*)d_out;

    float *h, *m, *s3, *w3c, *qkv, *tmp, *g;
    __nv_bfloat16 *nf_h, *nf_l, *wn_h, *wn_l, *gw_h, *gw_l, *wqkv_h, *wqkv_l;
    __nv_bfloat16 *ff1_h, *ff1_l, *ff2_h, *ff2_l, *g1_h, *g1_l;
    __nv_bfloat16 *hx_h, *hx_l, *ffx_h, *ffx_l;
    cudaGetSymbolAddress((void**)&h,    d_h);
    cudaGetSymbolAddress((void**)&m,    d_m);
    cudaGetSymbolAddress((void**)&s3,   d_s3);
    cudaGetSymbolAddress((void**)&w3c,  d_w3c);
    cudaGetSymbolAddress((void**)&qkv,  d_qkv);
    cudaGetSymbolAddress((void**)&tmp,  d_tmp);
    cudaGetSymbolAddress((void**)&g,    d_g);
    cudaGetSymbolAddress((void**)&nf_h, d_nf_h);  cudaGetSymbolAddress((void**)&nf_l, d_nf_l);
    cudaGetSymbolAddress((void**)&wn_h, d_wn_h);  cudaGetSymbolAddress((void**)&wn_l, d_wn_l);
    cudaGetSymbolAddress((void**)&gw_h, d_gw_h);  cudaGetSymbolAddress((void**)&gw_l, d_gw_l);
    cudaGetSymbolAddress((void**)&wqkv_h, d_wqkv_h); cudaGetSymbolAddress((void**)&wqkv_l, d_wqkv_l);
    cudaGetSymbolAddress((void**)&ff1_h, d_ff1_h); cudaGetSymbolAddress((void**)&ff1_l, d_ff1_l);
    cudaGetSymbolAddress((void**)&ff2_h, d_ff2_h); cudaGetSymbolAddress((void**)&ff2_l, d_ff2_l);
    cudaGetSymbolAddress((void**)&g1_h, d_g1_h);  cudaGetSymbolAddress((void**)&g1_l, d_g1_l);
    cudaGetSymbolAddress((void**)&hx_h, d_hx_h);  cudaGetSymbolAddress((void**)&hx_l, d_hx_l);
    cudaGetSymbolAddress((void**)&ffx_h, d_ffx_h); cudaGetSymbolAddress((void**)&ffx_l, d_ffx_l);

    static bool attr_done = false;
    if (!attr_done) {
        cudaFuncSetAttribute(gemm_bf3, cudaFuncAttributeMaxDynamicSharedMemorySize, GEMM_SMEM_BYTES);
        cudaFuncSetAttribute(gat_fused_kernel, cudaFuncAttributeMaxDynamicSharedMemorySize, GAT_SMEM_BYTES);
        attr_done = true;
    }

    // Launch order arranged so ncu (-s 5 -c 1) captures launch #6 =
    // the GAT layer-0 HD GEMM (gemm_bf3).
    // 1: merged weight prep
    prep_weights_kernel<<<(PREPW_TOTAL + 255)/256, 256>>>(
        Wn, gat_W, ff_W1, ff_W2, g_W1, Wq, Wk, Wv,
        wn_h, wn_l, gw_h, gw_l, ff1_h, ff1_l, ff2_h, ff2_l, g1_h, g1_l, wqkv_h, wqkv_l);
    // 2: node_feats split
    prep_nf_kernel<<<(NN*NODE_IN + 255)/256, 256>>>(node_feats, nf_h, nf_l);
    // 3-4: edge precompute
    edge_w3_all_kernel<<<1, NL*33>>>(We, be, gat_a, w3c);
    edge_s3_all_kernel<<<NE/8, 256>>>(edge_feats, w3c, s3);
    // 5: input projection  h = node_feats @ Wn + bn
    gemm_bf3<<<dim3(HD/BN, NN/BM), 256, GEMM_SMEM_BYTES>>>(
        nf_h, nf_l, wn_h, wn_l, bn, h, hx_h, hx_l, NN, HD, NODE_IN, 0);

    // GAT layers (launch 6 = layer-0 GEMM -> profiled)
    for (int l = 0; l < NL; l++) {
        gemm_bf3<<<dim3(HD/BN, NN/BM), 256, GEMM_SMEM_BYTES>>>(
            hx_h, hx_l, gw_h + (size_t)l*HD*HD, gw_l + (size_t)l*HD*HD,
            nullptr, m, nullptr, nullptr, NN, HD, HD, 0);
        gat_fused_kernel<<<NB, 256, GAT_SMEM_BYTES>>>(
            m, dst, s3 + (size_t)l*NE, gat_a + (size_t)l*3*HD,
            gat_lng + l*HD, gat_lnb + l*HD, h, hx_h, hx_l);
    }

    // QKV + attention + LN
    gemm_bf3<<<dim3(QKV3/BN, NN/BM), 256, GEMM_SMEM_BYTES>>>(
        hx_h, hx_l, wqkv_h, wqkv_l, nullptr, qkv, nullptr, nullptr, NN, QKV3, HD, 0);
    mha_kernel<<<NB * HEADS, NPG>>>(qkv, tmp);
    add_ln_kernel<<<NN, 256>>>(tmp, h, att_lng, att_lnb, 1e-6f, h, hx_h, hx_l);

    // FFN
    gemm_bf3<<<dim3(FF/BN, NN/BM), 256, GEMM_SMEM_BYTES>>>(
        hx_h, hx_l, ff1_h, ff1_l, ff_b1, nullptr, ffx_h, ffx_l, NN, FF, HD, 2);
    gemm_bf3<<<dim3(HD/BN, NN/BM), 256, GEMM_SMEM_BYTES>>>(
        ffx_h, ffx_l, ff2_h, ff2_l, ff_b2, tmp, nullptr, nullptr, NN, HD, FF, 0);
    add_ln_kernel<<<NN, 256>>>(h, tmp, ff_lng, ff_lnb, 1e-6f, h, hx_h, hx_l);

    // Gating readout
    gemm_bf3<<<dim3(HD/BN, NN/BM), 256, GEMM_SMEM_BYTES>>>(
        hx_h, hx_l, g1_h, g1_l, g_b1, m, nullptr, nullptr, NN, HD, HD, 1);
    gate_g_kernel<<<NN/8, 256>>>(m, g_W2, g_b2, g);
    readout_kernel<<<NB, HD>>>(h, g, out);

    (void)in_sizes; (void)n_in; (void)out_size;
}